// round 16
// baseline (speedup 1.0000x reference)
#include <cuda_runtime.h>
#include <cstdint>
#include <cstddef>

// ---------------------------------------------------------------------------
// PointSampler: jax threefry masked random-permutation sampling.
//   x [B,C,H,W] f32, mask [B,1,H,W] f32, k=4096
//   out = concat( samples[B,k,C], b_idx[B,k], h_idx[B,k], w_idx[B,k] ) f32
// keys (256 CTAs: threefry + per-chunk hist) ->
// select (16 CTAs: merge+scan, scatter, rank, pos-bucket grouping) ->
// gather (tiled transpose, 4096 CTAs, STS.128 staging, + idx outputs)
// ---------------------------------------------------------------------------

constexpr int B = 16, C = 256, H = 128, W = 128;
constexpr int L = H * W;          // 16384
constexpr int K = 4096;
constexpr int NB = 4096;          // bins = mkey>>11
constexpr int WIN = K + 256;      // scatter window
constexpr int NPROC = K + 128;    // slots ranked
constexpr int Q = 16;             // keys chunks per batch (256 CTAs total)

// select smem: mkey 64KB (aliased by rankpos after P3) + hist + pairs + hist2
constexpr int SMEM_SEL = 65536 + NB * 4 + WIN * 8 + 1056 * 4;

constexpr int PBLK = 32;          // pos-blocks of 512
constexpr int PB_POS = L / PBLK;  // 512
constexpr int PB_WIN = PB_POS / 128;  // 4 windows

__device__ uint32_t g_mkey[B * L];       // 23-bit key or 0x800000 sentinel
__device__ uint32_t g_hist[B * Q * NB];  // per-chunk histograms
__device__ uint32_t g_pos[B * K];        // rank -> flat position
__device__ uint32_t g_sel[B * K];        // 16-pos-bucket-grouped (pos<<16)|rank
__device__ uint32_t g_cidx[B * 1025];    // sel-index at 16-pos granularity
__device__ int      g_counts[B];

// ---- jax threefry2x32 (20 rounds), partitionable mode ---------------------
__device__ __forceinline__ uint32_t jax_bits(uint32_t n) {
    uint32_t k0 = 0u, k1 = 42u;
    uint32_t ks2 = k0 ^ k1 ^ 0x1BD11BDAu;
    uint32_t x0 = k0, x1 = n + k1;
#define TF_RND(r) { x0 += x1; x1 = __funnelshift_l(x1, x1, (r)); x1 ^= x0; }
    TF_RND(13) TF_RND(15) TF_RND(26) TF_RND(6)
    x0 += k1;  x1 += ks2 + 1u;
    TF_RND(17) TF_RND(29) TF_RND(16) TF_RND(24)
    x0 += ks2; x1 += k0 + 2u;
    TF_RND(13) TF_RND(15) TF_RND(26) TF_RND(6)
    x0 += k0;  x1 += k1 + 3u;
    TF_RND(17) TF_RND(29) TF_RND(16) TF_RND(24)
    x0 += k1;  x1 += ks2 + 4u;
    TF_RND(13) TF_RND(15) TF_RND(26) TF_RND(6)
    x0 += ks2; x1 += k0 + 5u;
#undef TF_RND
    return x0 ^ x1;
}

__device__ __forceinline__ uint32_t warp_incl_scan(uint32_t v) {
#pragma unroll
    for (int o = 1; o < 32; o <<= 1) {
        uint32_t u = __shfl_up_sync(0xFFFFFFFFu, v, o);
        if ((threadIdx.x & 31) >= o) v += u;
    }
    return v;
}

// ---- keys: threefry + mask -> g_mkey, plus per-chunk histogram ------------
__global__ __launch_bounds__(1024) void keys_kernel(const float* __restrict__ mask) {
    __shared__ uint32_t hist[NB];
    const int t = threadIdx.x;
    for (int i = t; i < NB; i += 1024) hist[i] = 0u;
    __syncthreads();
    int n = blockIdx.x * 1024 + t;          // 1 element per thread, 256 CTAs
    uint32_t bits = jax_bits((uint32_t)n);
    uint32_t mk = (mask[n] > 0.5f) ? (bits >> 9) : 0x800000u;
    g_mkey[n] = mk;
    if (mk < 0x800000u) atomicAdd(&hist[mk >> 11], 1u);
    __syncthreads();
    uint32_t* gh = g_hist + (size_t)blockIdx.x * NB;
    for (int i = t; i < NB; i += 1024) gh[i] = hist[i];
}

// ---- select: merge+scan, scatter, rank, K-wide pos-bucket grouping --------
__global__ __launch_bounds__(1024, 1) void select_kernel() {
    extern __shared__ unsigned char sm[];
    uint32_t* mkey  = (uint32_t*)sm;                            // 16384 u32
    uint32_t* hist  = (uint32_t*)(sm + 65536);                  // NB u32
    uint64_t* pairs = (uint64_t*)(sm + 65536 + NB * 4);         // WIN u64
    uint32_t* hist2 = (uint32_t*)(sm + 65536 + NB * 4 + WIN * 8); // 1056 u32
    uint32_t* rankpos = mkey;                                   // alias after P3
    __shared__ uint32_t wsum[32], wpre[32];
    __shared__ int sh_count;

    const int b = blockIdx.x;
    const int t = threadIdx.x;

    // P0: zero hist2, merge per-chunk histograms (coalesced, no atomics)
    if (t < 1056) hist2[t] = 0u;
#pragma unroll
    for (int i = 0; i < 4; i++) {
        int bin = i * 1024 + t;
        uint32_t s = 0;
#pragma unroll
        for (int q = 0; q < Q; q++)
            s += __ldg(&g_hist[((size_t)(b * Q + q)) * NB + bin]);
        hist[bin] = s;
    }

    // P1: load mkey into smem (vectorized)
#pragma unroll
    for (int i = 0; i < 4; i++) {
        int l4 = i * 1024 + t;
        *((uint4*)mkey + l4) = __ldg((const uint4*)(g_mkey + b * L) + l4);
    }
    __syncthreads();

    // P2: exclusive scan of 4096 bins (warp shuffles, 2 barriers)
    uint32_t h4[4];
    uint32_t s = 0;
#pragma unroll
    for (int i = 0; i < 4; i++) { h4[i] = hist[t * 4 + i]; s += h4[i]; }
    uint32_t incl = warp_incl_scan(s);
    if ((t & 31) == 31) wsum[t >> 5] = incl;
    __syncthreads();
    if (t < 32) { uint32_t v = wsum[t]; uint32_t iv = warp_incl_scan(v); wpre[t] = iv - v; }
    __syncthreads();
    uint32_t run = wpre[t >> 5] + incl - s;
#pragma unroll
    for (int i = 0; i < 4; i++) { hist[t * 4 + i] = run; run += h4[i]; }
    if (t == 1023) sh_count = (int)run;
    __syncthreads();
    const int count = sh_count;
    if (t == 0) g_counts[b] = count;

    // P3: scatter masked keys into bin slots (window only)
#pragma unroll
    for (int i = 0; i < 16; i++) {
        int l = i * 1024 + t;
        uint32_t mk = mkey[l];
        if (mk < 0x800000u) {
            uint32_t slot = atomicAdd(&hist[mk >> 11], 1u);
            if (slot < (uint32_t)WIN)
                pairs[slot] = (((uint64_t)mk) << 14) | (uint64_t)l;
        }
    }
    __syncthreads();        // mkey dead; rankpos aliases it

    // P4: rank fixup; ranked entries feed rankpos + pos-bucket histogram
    const int nwin  = (count < WIN) ? count : WIN;
    const int nproc = (count < NPROC) ? count : NPROC;
    for (int sI = t; sI < nproc; sI += 1024) {
        uint64_t kv = pairs[sI];
        uint32_t bn = (uint32_t)(kv >> 25);
        int g = sI;
        while (g > 0 && (uint32_t)(pairs[g - 1] >> 25) == bn) g--;
        int r = 0;
        for (int u = g; u < nwin; u++) {
            uint64_t pk = pairs[u];
            if ((uint32_t)(pk >> 25) != bn) break;
            if (pk < kv) r++;
        }
        int rank = g + r;
        if (rank < K) {
            uint32_t p = (uint32_t)(kv & (uint64_t)(L - 1));
            g_pos[b * K + rank] = p;
            rankpos[rank] = p;
            atomicAdd(&hist2[p >> 4], 1u);
        }
    }
    __syncthreads();

    // P5: scan 1024 pos-buckets -> g_cidx; K-wide scatter -> g_sel
    const int nsel = (count < K) ? count : K;
    {
        uint32_t v = hist2[t];
        uint32_t incl2 = warp_incl_scan(v);
        if ((t & 31) == 31) wsum[t >> 5] = incl2;
        __syncthreads();
        if (t < 32) { uint32_t w2 = wsum[t]; uint32_t iv = warp_incl_scan(w2); wpre[t] = iv - w2; }
        __syncthreads();
        uint32_t excl = wpre[t >> 5] + incl2 - v;
        g_cidx[b * 1025 + t] = excl;
        hist2[t] = excl;                    // running cursor
        if (t == 1023) g_cidx[b * 1025 + 1024] = (uint32_t)nsel;
    }
    __syncthreads();
    for (int j = t; j < nsel; j += 1024) {
        uint32_t p = rankpos[j];
        uint32_t slot = atomicAdd(&hist2[p >> 4], 1u);
        g_sel[b * K + slot] = (p << 16) | (uint32_t)j;
    }
}

// ---- gather: tiled transpose + idx outputs, fine-grained tail -------------
__global__ __launch_bounds__(256) void gather_kernel(
        const float* __restrict__ x, float* __restrict__ out, int out_size) {
    // stride 132 floats: row offsets 16B-aligned -> STS.128, conflict-free.
    __shared__ __align__(16) float tile[32][132];

    const int pblk = blockIdx.x;             // 32 pos-blocks of 512
    const int cblk = blockIdx.y;             // 8 c-blocks of 32
    const int b    = blockIdx.z;
    const int t = threadIdx.x;
    const int w = t >> 5, lane = t & 31;

    const int cb = g_counts[b];

    // idx outputs (cblk==0 CTAs): 128 j's each, hidden under DRAM time
    if (cblk == 0 && t < (K / PBLK)) {
        size_t off = (size_t)B * K * C;
        if ((size_t)out_size >= off + 3u * (size_t)(B * K) && cb > 0) {
            int j = pblk * (K / PBLK) + t;
            int eff = (j < cb) ? j : (j % cb);
            uint32_t p = __ldg(&g_pos[b * K + eff]);
            size_t i = (size_t)b * K + j;
            out[off + i] = (float)b;
            out[off + (size_t)(B * K) + i] = (float)(p >> 7);
            out[off + 2u * (size_t)(B * K) + i] = (float)(p & (W - 1));
        }
    }

    const int c0 = cblk * 32;
    const float* xb = x + ((size_t)(b * C + c0)) * (size_t)L;
    const int pbase0 = pblk * PB_POS;
    const uint32_t* cidx = g_cidx + b * 1025 + pblk * (PB_POS / 16);
    const uint32_t* selb = g_sel + b * K;

    for (int pw = 0; pw < PB_WIN; pw++) {
        const int pbase = pbase0 + pw * 128;

        // load 32 channels x 128 pos, fully coalesced float4, STS.128 staging
        float4 v[4];
#pragma unroll
        for (int r = 0; r < 4; r++)
            v[r] = __ldg((const float4*)(xb + (size_t)(w + 8 * r) * L + pbase) + lane);
#pragma unroll
        for (int r = 0; r < 4; r++)
            *(float4*)&tile[w + 8 * r][lane * 4] = v[r];
        __syncthreads();

        // extract selected entries in this pos window
        const int s = (int)__ldg(&cidx[pw * 8]);
        const int e = (int)__ldg(&cidx[pw * 8 + 8]);
        for (int idx = s + w; idx < e; idx += 8) {
            uint32_t ent = __ldg(&selb[idx]);               // broadcast
            int p  = (int)(ent >> 16) - pbase;
            int rk = (int)(ent & 0xFFFFu);
            float val = tile[lane][p];
            out[((size_t)b * K + rk) * (size_t)C + c0 + lane] = val;  // 128B line
        }
        __syncthreads();
    }

    // wrap fallback (count < K) — no-op in practice
    if (cb > 0 && cb < K && pblk == 0) {
        for (int j = cb + t; j < K; j += 256) {
            uint32_t p = g_pos[b * K + (j % cb)];
            for (int cc = 0; cc < 32; cc++)
                out[((size_t)b * K + j) * (size_t)C + c0 + cc] =
                    __ldg(&x[((size_t)(b * C + c0 + cc)) * (size_t)L + p]);
        }
    }
}

extern "C" void kernel_launch(void* const* d_in, const int* in_sizes, int n_in,
                              void* d_out, int out_size) {
    const float* x = (const float*)d_in[0];
    int mi = n_in - 1;
    for (int i = 1; i < n_in; i++)
        if (in_sizes[i] == B * L) { mi = i; break; }
    const float* mask = (const float*)d_in[mi];
    float* out = (float*)d_out;

    static bool attr_done = false;
    if (!attr_done) {
        cudaFuncSetAttribute(select_kernel,
                             cudaFuncAttributeMaxDynamicSharedMemorySize, SMEM_SEL);
        attr_done = true;
    }

    keys_kernel<<<B * Q, 1024>>>(mask);
    select_kernel<<<B, 1024, SMEM_SEL>>>();
    dim3 gg(PBLK, 8, B);
    gather_kernel<<<gg, 256>>>(x, out, out_size);
}

// round 17
// speedup vs baseline: 1.0156x; 1.0156x over previous
#include <cuda_runtime.h>
#include <cstdint>
#include <cstddef>

// ---------------------------------------------------------------------------
// PointSampler: jax threefry masked random-permutation sampling.
//   x [B,C,H,W] f32, mask [B,1,H,W] f32, k=4096
//   out = concat( samples[B,k,C], b_idx[B,k], h_idx[B,k], w_idx[B,k] ) f32
// keys (128 CTAs: threefry + packed-u16 per-chunk hist) ->
// select (16 CTAs: merge+scan, scatter, rank, pos-bucket grouping) ->
// gather (tiled transpose, 4096 CTAs, STS.128 staging, + idx outputs)
// ---------------------------------------------------------------------------

constexpr int B = 16, C = 256, H = 128, W = 128;
constexpr int L = H * W;          // 16384
constexpr int K = 4096;
constexpr int NB = 4096;          // bins = mkey>>11
constexpr int WIN = K + 256;      // scatter window
constexpr int NPROC = K + 128;    // slots ranked
constexpr int Q = 8;              // keys chunks per batch (128 CTAs)

// select smem: hist 16KB @0 | pairs @16384 | hist2 @51200 | rankpos @55424
constexpr int SMEM_SEL = 71808;

constexpr int PBLK = 32;          // pos-blocks of 512
constexpr int PB_POS = L / PBLK;  // 512
constexpr int PB_WIN = PB_POS / 128;  // 4 windows

__device__ uint32_t g_mkey[B * L];            // 23-bit key or 0x800000 sentinel
__device__ uint32_t g_hist[B * Q * (NB / 2)]; // packed u16 pairs per chunk
__device__ uint32_t g_pos[B * K];             // rank -> flat position
__device__ uint32_t g_sel[B * K];             // 16-pos-bucket-grouped (pos<<16)|rank
__device__ uint32_t g_cidx[B * 1025];         // sel-index at 16-pos granularity
__device__ int      g_counts[B];

// ---- jax threefry2x32 (20 rounds), partitionable mode ---------------------
__device__ __forceinline__ uint32_t jax_bits(uint32_t n) {
    uint32_t k0 = 0u, k1 = 42u;
    uint32_t ks2 = k0 ^ k1 ^ 0x1BD11BDAu;
    uint32_t x0 = k0, x1 = n + k1;
#define TF_RND(r) { x0 += x1; x1 = __funnelshift_l(x1, x1, (r)); x1 ^= x0; }
    TF_RND(13) TF_RND(15) TF_RND(26) TF_RND(6)
    x0 += k1;  x1 += ks2 + 1u;
    TF_RND(17) TF_RND(29) TF_RND(16) TF_RND(24)
    x0 += ks2; x1 += k0 + 2u;
    TF_RND(13) TF_RND(15) TF_RND(26) TF_RND(6)
    x0 += k0;  x1 += k1 + 3u;
    TF_RND(17) TF_RND(29) TF_RND(16) TF_RND(24)
    x0 += k1;  x1 += ks2 + 4u;
    TF_RND(13) TF_RND(15) TF_RND(26) TF_RND(6)
    x0 += ks2; x1 += k0 + 5u;
#undef TF_RND
    return x0 ^ x1;
}

__device__ __forceinline__ uint32_t warp_incl_scan(uint32_t v) {
#pragma unroll
    for (int o = 1; o < 32; o <<= 1) {
        uint32_t u = __shfl_up_sync(0xFFFFFFFFu, v, o);
        if ((threadIdx.x & 31) >= o) v += u;
    }
    return v;
}

// ---- keys: threefry + mask -> g_mkey, plus packed per-chunk histogram -----
__global__ __launch_bounds__(1024) void keys_kernel(const float* __restrict__ mask) {
    __shared__ uint32_t hist[NB];
    const int t = threadIdx.x;
    for (int i = t; i < NB; i += 1024) hist[i] = 0u;
    __syncthreads();
    int n0 = blockIdx.x * 2048 + t;
#pragma unroll
    for (int i = 0; i < 2; i++) {
        int n = n0 + i * 1024;
        uint32_t bits = jax_bits((uint32_t)n);
        uint32_t mk = (mask[n] > 0.5f) ? (bits >> 9) : 0x800000u;
        g_mkey[n] = mk;
        if (mk < 0x800000u) atomicAdd(&hist[mk >> 11], 1u);
    }
    __syncthreads();
    // writeback packed: one u32 carries bins (2i, 2i+1) as u16 lanes
    uint32_t* gh = g_hist + (size_t)blockIdx.x * (NB / 2);
    for (int i = t; i < NB / 2; i += 1024)
        gh[i] = hist[2 * i] | (hist[2 * i + 1] << 16);
}

// ---- select: merge+scan, scatter, rank, K-wide pos-bucket grouping --------
__global__ __launch_bounds__(1024, 1) void select_kernel() {
    extern __shared__ unsigned char sm[];
    uint32_t* hist    = (uint32_t*)sm;                  // 4096 u32
    uint64_t* pairs   = (uint64_t*)(sm + 16384);        // WIN u64
    uint32_t* hist2   = (uint32_t*)(sm + 51200);        // 1056 u32
    uint32_t* rankpos = (uint32_t*)(sm + 55424);        // 4096 u32
    __shared__ uint32_t wsum[32], wpre[32];
    __shared__ int sh_count;

    const int b = blockIdx.x;
    const int t = threadIdx.x;

    // P0: zero hist2; merge packed per-chunk histograms (u32 adds, no carry:
    // per-bin sum <= 8*2048 = 16384 < 65536)
    if (t < 1056) hist2[t] = 0u;
#pragma unroll
    for (int i = 0; i < 2; i++) {
        int pk = i * 1024 + t;                  // packed index, 2048 total
        uint32_t s = 0;
#pragma unroll
        for (int q = 0; q < Q; q++)
            s += __ldg(&g_hist[((size_t)(b * Q + q)) * (NB / 2) + pk]);
        hist[2 * pk]     = s & 0xFFFFu;
        hist[2 * pk + 1] = s >> 16;
    }
    __syncthreads();

    // P2: exclusive scan of 4096 bins (warp shuffles, 2 barriers)
    uint32_t h4[4];
    uint32_t s = 0;
#pragma unroll
    for (int i = 0; i < 4; i++) { h4[i] = hist[t * 4 + i]; s += h4[i]; }
    uint32_t incl = warp_incl_scan(s);
    if ((t & 31) == 31) wsum[t >> 5] = incl;
    __syncthreads();
    if (t < 32) { uint32_t v = wsum[t]; uint32_t iv = warp_incl_scan(v); wpre[t] = iv - v; }
    __syncthreads();
    uint32_t run = wpre[t >> 5] + incl - s;
#pragma unroll
    for (int i = 0; i < 4; i++) { hist[t * 4 + i] = run; run += h4[i]; }
    if (t == 1023) sh_count = (int)run;
    __syncthreads();
    const int count = sh_count;
    if (t == 0) g_counts[b] = count;

    // P3: scatter masked keys (coalesced re-read of g_mkey) into bin slots
#pragma unroll
    for (int i = 0; i < 16; i++) {
        int l = i * 1024 + t;
        uint32_t mk = __ldg(&g_mkey[b * L + l]);
        if (mk < 0x800000u) {
            uint32_t slot = atomicAdd(&hist[mk >> 11], 1u);
            if (slot < (uint32_t)WIN)
                pairs[slot] = (((uint64_t)mk) << 14) | (uint64_t)l;
        }
    }
    __syncthreads();

    // P4: rank fixup; ranked entries feed rankpos + pos-bucket histogram
    const int nwin  = (count < WIN) ? count : WIN;
    const int nproc = (count < NPROC) ? count : NPROC;
    for (int sI = t; sI < nproc; sI += 1024) {
        uint64_t kv = pairs[sI];
        uint32_t bn = (uint32_t)(kv >> 25);
        int g = sI;
        while (g > 0 && (uint32_t)(pairs[g - 1] >> 25) == bn) g--;
        int r = 0;
        for (int u = g; u < nwin; u++) {
            uint64_t pk = pairs[u];
            if ((uint32_t)(pk >> 25) != bn) break;
            if (pk < kv) r++;
        }
        int rank = g + r;
        if (rank < K) {
            uint32_t p = (uint32_t)(kv & (uint64_t)(L - 1));
            g_pos[b * K + rank] = p;
            rankpos[rank] = p;
            atomicAdd(&hist2[p >> 4], 1u);
        }
    }
    __syncthreads();

    // P5: scan 1024 pos-buckets -> g_cidx; K-wide scatter -> g_sel
    const int nsel = (count < K) ? count : K;
    {
        uint32_t v = hist2[t];
        uint32_t incl2 = warp_incl_scan(v);
        if ((t & 31) == 31) wsum[t >> 5] = incl2;
        __syncthreads();
        if (t < 32) { uint32_t w2 = wsum[t]; uint32_t iv = warp_incl_scan(w2); wpre[t] = iv - w2; }
        __syncthreads();
        uint32_t excl = wpre[t >> 5] + incl2 - v;
        g_cidx[b * 1025 + t] = excl;
        hist2[t] = excl;                    // running cursor
        if (t == 1023) g_cidx[b * 1025 + 1024] = (uint32_t)nsel;
    }
    __syncthreads();
    for (int j = t; j < nsel; j += 1024) {
        uint32_t p = rankpos[j];
        uint32_t slot = atomicAdd(&hist2[p >> 4], 1u);
        g_sel[b * K + slot] = (p << 16) | (uint32_t)j;
    }
}

// ---- gather: tiled transpose + idx outputs, fine-grained tail -------------
__global__ __launch_bounds__(256) void gather_kernel(
        const float* __restrict__ x, float* __restrict__ out, int out_size) {
    // stride 132 floats: row offsets 16B-aligned -> STS.128, conflict-free.
    __shared__ __align__(16) float tile[32][132];

    const int pblk = blockIdx.x;             // 32 pos-blocks of 512
    const int cblk = blockIdx.y;             // 8 c-blocks of 32
    const int b    = blockIdx.z;
    const int t = threadIdx.x;
    const int w = t >> 5, lane = t & 31;

    const int cb = g_counts[b];

    // idx outputs (cblk==0 CTAs): 128 j's each, hidden under DRAM time
    if (cblk == 0 && t < (K / PBLK)) {
        size_t off = (size_t)B * K * C;
        if ((size_t)out_size >= off + 3u * (size_t)(B * K) && cb > 0) {
            int j = pblk * (K / PBLK) + t;
            int eff = (j < cb) ? j : (j % cb);
            uint32_t p = __ldg(&g_pos[b * K + eff]);
            size_t i = (size_t)b * K + j;
            out[off + i] = (float)b;
            out[off + (size_t)(B * K) + i] = (float)(p >> 7);
            out[off + 2u * (size_t)(B * K) + i] = (float)(p & (W - 1));
        }
    }

    const int c0 = cblk * 32;
    const float* xb = x + ((size_t)(b * C + c0)) * (size_t)L;
    const int pbase0 = pblk * PB_POS;
    const uint32_t* cidx = g_cidx + b * 1025 + pblk * (PB_POS / 16);
    const uint32_t* selb = g_sel + b * K;

    for (int pw = 0; pw < PB_WIN; pw++) {
        const int pbase = pbase0 + pw * 128;

        // load 32 channels x 128 pos, fully coalesced float4, STS.128 staging
        float4 v[4];
#pragma unroll
        for (int r = 0; r < 4; r++)
            v[r] = __ldg((const float4*)(xb + (size_t)(w + 8 * r) * L + pbase) + lane);
#pragma unroll
        for (int r = 0; r < 4; r++)
            *(float4*)&tile[w + 8 * r][lane * 4] = v[r];
        __syncthreads();

        // extract selected entries in this pos window
        const int s = (int)__ldg(&cidx[pw * 8]);
        const int e = (int)__ldg(&cidx[pw * 8 + 8]);
        for (int idx = s + w; idx < e; idx += 8) {
            uint32_t ent = __ldg(&selb[idx]);               // broadcast
            int p  = (int)(ent >> 16) - pbase;
            int rk = (int)(ent & 0xFFFFu);
            float val = tile[lane][p];
            out[((size_t)b * K + rk) * (size_t)C + c0 + lane] = val;  // 128B line
        }
        __syncthreads();
    }

    // wrap fallback (count < K) — no-op in practice
    if (cb > 0 && cb < K && pblk == 0) {
        for (int j = cb + t; j < K; j += 256) {
            uint32_t p = g_pos[b * K + (j % cb)];
            for (int cc = 0; cc < 32; cc++)
                out[((size_t)b * K + j) * (size_t)C + c0 + cc] =
                    __ldg(&x[((size_t)(b * C + c0 + cc)) * (size_t)L + p]);
        }
    }
}

extern "C" void kernel_launch(void* const* d_in, const int* in_sizes, int n_in,
                              void* d_out, int out_size) {
    const float* x = (const float*)d_in[0];
    int mi = n_in - 1;
    for (int i = 1; i < n_in; i++)
        if (in_sizes[i] == B * L) { mi = i; break; }
    const float* mask = (const float*)d_in[mi];
    float* out = (float*)d_out;

    static bool attr_done = false;
    if (!attr_done) {
        cudaFuncSetAttribute(select_kernel,
                             cudaFuncAttributeMaxDynamicSharedMemorySize, SMEM_SEL);
        attr_done = true;
    }

    keys_kernel<<<B * Q, 1024>>>(mask);
    select_kernel<<<B, 1024, SMEM_SEL>>>();
    dim3 gg(PBLK, 8, B);
    gather_kernel<<<gg, 256>>>(x, out, out_size);
}